// round 15
// baseline (speedup 1.0000x reference)
#include <cuda_runtime.h>

// w: [4096, 4096] fp32. Hinv1 dead (LAMBDA=1.0), bit_width fixed at 3.
#define NROWS 4096
#define NCOLS 4096
#define NTHREADS 256
#define EPT (NCOLS / NTHREADS)
#define NCAND 101

__device__ __forceinline__ float fast_lg2(float x) {
    float y; asm("lg2.approx.f32 %0, %1;" : "=f"(y) : "f"(x)); return y;
}
__device__ __forceinline__ float fast_ex2(float x) {
    float y; asm("ex2.approx.f32 %0, %1;" : "=f"(y) : "f"(x)); return y;
}

// ---- packed f32x2 helpers (Blackwell sm_103a) ----
__device__ __forceinline__ unsigned long long pk2(float lo, float hi) {
    unsigned long long o;
    asm("mov.b64 %0, {%1, %2};" : "=l"(o) : "f"(lo), "f"(hi));
    return o;
}
__device__ __forceinline__ void upk2(float& lo, float& hi, unsigned long long p) {
    asm("mov.b64 {%0, %1}, %2;" : "=f"(lo), "=f"(hi) : "l"(p));
}
__device__ __forceinline__ unsigned long long mul2(unsigned long long a, unsigned long long b) {
    unsigned long long o;
    asm("mul.rn.f32x2 %0, %1, %2;" : "=l"(o) : "l"(a), "l"(b));
    return o;
}
__device__ __forceinline__ unsigned long long add2(unsigned long long a, unsigned long long b) {
    unsigned long long o;
    asm("add.rn.f32x2 %0, %1, %2;" : "=l"(o) : "l"(a), "l"(b));
    return o;
}
__device__ __forceinline__ unsigned long long sub2(unsigned long long a, unsigned long long b) {
    unsigned long long o;
    asm("sub.rn.f32x2 %0, %1, %2;" : "=l"(o) : "l"(a), "l"(b));
    return o;
}
__device__ __forceinline__ unsigned long long fma2(unsigned long long a, unsigned long long b,
                                                   unsigned long long c) {
    unsigned long long o;
    asm("fma.rn.f32x2 %0, %1, %2, %3;" : "=l"(o) : "l"(a), "l"(b), "l"(c));
    return o;
}
__device__ __forceinline__ unsigned long long abs2(unsigned long long a) {
    return a & 0x7FFFFFFF7FFFFFFFull;
}

// ---- f16x2 helpers ----
__device__ __forceinline__ unsigned cvt_f16x2(float hi, float lo) {
    unsigned r; asm("cvt.rn.f16x2.f32 %0, %1, %2;" : "=r"(r) : "f"(hi), "f"(lo));
    return r;
}
__device__ __forceinline__ unsigned ex2h2(unsigned x) {
    unsigned r; asm("ex2.approx.f16x2 %0, %1;" : "=r"(r) : "r"(x));
    return r;
}
__device__ __forceinline__ unsigned hadd2(unsigned a, unsigned b) {
    unsigned o; asm("add.rn.f16x2 %0, %1, %2;" : "=r"(o) : "r"(a), "r"(b));
    return o;
}
__device__ __forceinline__ void h2_to_f32(float& lo, float& hi, unsigned h) {
    asm("{\n\t.reg .b16 l, u;\n\t"
        "mov.b32 {l, u}, %2;\n\t"
        "cvt.f32.f16 %0, l;\n\t"
        "cvt.f32.f16 %1, u;\n\t}" : "=f"(lo), "=f"(hi) : "r"(h));
}

// Candidate shrink factors in reference scan order.
__device__ __forceinline__ float pcand(int c) {
    const float delta = 0.1f / 50.0f;
    if (c == 0) return 1.0f;
    if (c <= 50) return fmaf(delta, (float)c, 1.0f);
    return fmaf(-delta, (float)(c - 50), 1.0f);
}

#define MAGIC2 25165824.0f   // 3*2^23 : even-grain magic -> R = 2*rint(q/2)

// Degree-4 Chebyshev truncation of x^2.4 on [0,1], abs err <= ~4e-4.
#define Q0  0.000403f
#define Q1 -0.024680f
#define Q2  0.517810f
#define Q3  0.644350f
#define Q4 -0.138060f

__global__ __launch_bounds__(NTHREADS, 4) void quant_search_kernel(
    const float* __restrict__ w, float* __restrict__ out)
{
    __shared__ __align__(16) float sact[NCOLS];  // interior front, boundary back
    __shared__ float sS[NCAND];
    __shared__ float sI[NCAND];
    __shared__ float sC[NCAND];                  // (s/2)^2.4 * 2^B per candidate
    __shared__ float serr[NCAND * 8];
    __shared__ float stot[NCAND];
    __shared__ float smn[8], smx[8];
    __shared__ float sscale;
    __shared__ int   scnt_i, scnt_b;

    const int row  = blockIdx.x;
    const int tid  = threadIdx.x;
    const int lane = tid & 31;
    const int wid  = tid >> 5;
    const float* __restrict__ wrow = w + (size_t)row * NCOLS;

    if (tid == 0) { scnt_i = 0; scnt_b = 0; }

    // ---- Load row; min/max vs 0 (reference semantics) ----
    float wv[EPT];
    float mn = 0.0f, mx = 0.0f;
    #pragma unroll
    for (int k = 0; k < EPT; k++) {
        wv[k] = wrow[tid + k * NTHREADS];
        mn = fminf(mn, wv[k]);
        mx = fmaxf(mx, wv[k]);
    }
    #pragma unroll
    for (int o = 16; o > 0; o >>= 1) {
        mn = fminf(mn, __shfl_xor_sync(0xffffffffu, mn, o));
        mx = fmaxf(mx, __shfl_xor_sync(0xffffffffu, mx, o));
    }
    if (lane == 0) { smn[wid] = mn; smx[wid] = mx; }
    __syncthreads();

    float xmin = smn[0], xmax = smx[0];
    #pragma unroll
    for (int k = 1; k < 8; k++) {
        xmin = fminf(xmin, smn[k]);
        xmax = fmaxf(xmax, smx[k]);
    }
    if (xmin == 0.0f && xmax == 0.0f) { xmin = -1.0f; xmax = 1.0f; }
    const float rng = xmax - xmin;

    const float s_min = pcand(NCAND - 1) * rng / 7.0f;
    const float thr_p  = 0.49999f * s_min;   // prune: rint=0 for every candidate
    const float thr_hi = 3.4999f  * s_min;   // interior: clamp can never fire
    const float thr_lo = -4.4999f * s_min;

    // Per-row exponent bias (argmin-invariant global factor 2^B).
    const float B = fmaf(-2.4f, fast_lg2(rng), 11.5376f);

    if (tid < NCAND) {
        float s = pcand(tid) * rng / 7.0f;
        sS[tid] = s;
        sI[tid] = 1.0f / s;
        sC[tid] = fast_ex2(fmaf(2.4f, fast_lg2(0.5f * s), B));  // (s/2)^2.4 * 2^B
    }

    // ---- Two-class compaction (order irrelevant to fp-tolerant argmin) ----
    int ci = 0, cb = 0;
    #pragma unroll
    for (int k = 0; k < EPT; k++) {
        bool active = fabsf(wv[k]) > thr_p;
        bool inter  = active && (wv[k] < thr_hi) && (wv[k] > thr_lo);
        ci += inter ? 1 : 0;
        cb += (active && !inter) ? 1 : 0;
    }
    int bi_ = (ci > 0) ? atomicAdd(&scnt_i, ci) : 0;
    int bb_ = (cb > 0) ? atomicAdd(&scnt_b, cb) : 0;
    #pragma unroll
    for (int k = 0; k < EPT; k++) {
        bool active = fabsf(wv[k]) > thr_p;
        bool inter  = active && (wv[k] < thr_hi) && (wv[k] > thr_lo);
        if (inter) sact[bi_++] = wv[k];
        else if (active) sact[NCOLS - 1 - (bb_++)] = wv[k];
    }
    __syncthreads();
    const int nint   = scnt_i;
    const int nbnd   = scnt_b;
    const int nquads = nint >> 2;        // 4 elements per iteration
    const int ntail  = nint & 3;         // 0..3 interior leftovers -> scalar loop

    const unsigned long long MG2 = pk2(MAGIC2, MAGIC2);
    const unsigned long long C0 = pk2(Q0, Q0), C1 = pk2(Q1, Q1), C2 = pk2(Q2, Q2);
    const unsigned long long C3 = pk2(Q3, Q3), C4 = pk2(Q4, Q4);
    // Packed-f32x2 view of compacted actives: .x = floats[4i],[4i+1], .y = [4i+2],[4i+3]
    const ulonglong2* __restrict__ sact2 = reinterpret_cast<const ulonglong2*>(sact);

    // ---- Candidate search: 25 tiles of 4 (2 f16-MUFU + 2 fma-poly-d4), then cand 100
    // All candidates use jj = 2/s and the even-grain magic: R = 2*rint(u).
    // f16 path: d = fma(-s/2, R, v) == fma(-s, r, v) bit-identically.
    for (int ct = 0; ct < NCAND - 1; ct += 4) {
        const float s0 = sS[ct],  s1 = sS[ct+1], s2 = sS[ct+2], s3 = sS[ct+3];
        const float i0 = sI[ct],  i1 = sI[ct+1], i2 = sI[ct+2], i3 = sI[ct+3];
        const float j0 = 2.0f * i0, j1 = 2.0f * i1, j2 = 2.0f * i2, j3 = 2.0f * i3;
        const unsigned long long jj0 = pk2(j0, j0), jj1 = pk2(j1, j1);
        const unsigned long long jj2 = pk2(j2, j2), jj3 = pk2(j3, j3);
        const float h0 = -0.5f * s0, h1 = -0.5f * s1;
        const unsigned long long nh0 = pk2(h0, h0), nh1 = pk2(h1, h1);
        // Dual accumulators per candidate (independent chains per quad-half)
        unsigned hc0a = 0u, hc0b = 0u, hc1a = 0u, hc1b = 0u;
        unsigned long long p2a = 0ull, p2b = 0ull, p3a = 0ull, p3b = 0ull;

        for (int i = tid; i < nquads; i += NTHREADS) {
            const ulonglong2 vq = sact2[i];        // LDS.128 direct to packed regs
            const unsigned long long v2a = vq.x;
            const unsigned long long v2b = vq.y;

            // f16 path: term = ex2_h16(2.4*lg2|d| + B), accumulated in f16x2.
            #define F16_STEP(jj, nh, v2, acc) do {                         \
                unsigned long long q = mul2(v2, jj);                       \
                unsigned long long R = sub2(add2(q, MG2), MG2);            \
                unsigned long long d = fma2(nh, R, v2);                    \
                float dl, dh; upk2(dl, dh, d);                             \
                float x0 = fmaf(2.4f, fast_lg2(fabsf(dl)), B);             \
                float x1 = fmaf(2.4f, fast_lg2(fabsf(dh)), B);             \
                acc = hadd2(acc, ex2h2(cvt_f16x2(x1, x0))); } while (0)
            F16_STEP(jj0, nh0, v2a, hc0a);
            F16_STEP(jj0, nh0, v2b, hc0b);
            F16_STEP(jj1, nh1, v2a, hc1a);
            F16_STEP(jj1, nh1, v2b, hc1b);
            #undef F16_STEP

            // Poly path: t = q - R = 2(u - r); term = P4(|t|), scaled by sC[c].
            #define POLY_STEP(jj, v2, acc) do {                            \
                unsigned long long q = mul2(v2, jj);                       \
                unsigned long long R = sub2(add2(q, MG2), MG2);            \
                unsigned long long t = sub2(q, R);                         \
                unsigned long long at = abs2(t);                           \
                unsigned long long pp = fma2(C4, at, C3);                  \
                pp = fma2(pp, at, C2);                                     \
                pp = fma2(pp, at, C1);                                     \
                pp = fma2(pp, at, C0);                                     \
                acc = add2(acc, pp); } while (0)
            POLY_STEP(jj2, v2a, p2a);
            POLY_STEP(jj2, v2b, p2b);
            POLY_STEP(jj3, v2a, p3a);
            POLY_STEP(jj3, v2b, p3b);
            #undef POLY_STEP
        }

        float a0, a1, a2, a3, tl, th;
        h2_to_f32(tl, th, hadd2(hc0a, hc0b)); a0 = tl + th;
        h2_to_f32(tl, th, hadd2(hc1a, hc1b)); a1 = tl + th;
        upk2(tl, th, add2(p2a, p2b));         a2 = (tl + th) * sC[ct+2];
        upk2(tl, th, add2(p3a, p3b));         a3 = (tl + th) * sC[ct+3];

        // Boundary (+ interior tail 0..3): scalar f32 MUFU with clamps, biased.
        // Clamps never fire for interior tail elements -> identical math.
        for (int j = tid; j < nbnd + ntail; j += NTHREADS) {
            const float v = (j < nbnd) ? sact[NCOLS - 1 - j]
                                       : sact[4 * nquads + (j - nbnd)];
            float r;
            r = fminf(fmaxf(rintf(v * i0), -4.0f), 3.0f);
            a0 += fast_ex2(fmaf(2.4f, fast_lg2(fabsf(fmaf(s0, r, -v))), B));
            r = fminf(fmaxf(rintf(v * i1), -4.0f), 3.0f);
            a1 += fast_ex2(fmaf(2.4f, fast_lg2(fabsf(fmaf(s1, r, -v))), B));
            r = fminf(fmaxf(rintf(v * i2), -4.0f), 3.0f);
            a2 += fast_ex2(fmaf(2.4f, fast_lg2(fabsf(fmaf(s2, r, -v))), B));
            r = fminf(fmaxf(rintf(v * i3), -4.0f), 3.0f);
            a3 += fast_ex2(fmaf(2.4f, fast_lg2(fabsf(fmaf(s3, r, -v))), B));
        }

        #pragma unroll
        for (int o = 16; o > 0; o >>= 1) {
            a0 += __shfl_xor_sync(0xffffffffu, a0, o);
            a1 += __shfl_xor_sync(0xffffffffu, a1, o);
            a2 += __shfl_xor_sync(0xffffffffu, a2, o);
            a3 += __shfl_xor_sync(0xffffffffu, a3, o);
        }
        if (lane == 0) {
            serr[(ct    ) * 8 + wid] = a0;
            serr[(ct + 1) * 8 + wid] = a1;
            serr[(ct + 2) * 8 + wid] = a2;
            serr[(ct + 3) * 8 + wid] = a3;
        }
    }
    {   // candidate 100: scalar f32 MUFU path, biased
        const int c = NCAND - 1;
        const float s = sS[c], is = sI[c];
        float a = 0.0f;
        for (int i = tid; i < nint; i += NTHREADS) {
            const float v = sact[i];
            float r = rintf(v * is);
            a += fast_ex2(fmaf(2.4f, fast_lg2(fabsf(fmaf(s, r, -v))), B));
        }
        for (int j = tid; j < nbnd; j += NTHREADS) {
            const float v = sact[NCOLS - 1 - j];
            float r = fminf(fmaxf(rintf(v * is), -4.0f), 3.0f);
            a += fast_ex2(fmaf(2.4f, fast_lg2(fabsf(fmaf(s, r, -v))), B));
        }
        #pragma unroll
        for (int o = 16; o > 0; o >>= 1) a += __shfl_xor_sync(0xffffffffu, a, o);
        if (lane == 0) serr[c * 8 + wid] = a;
    }
    __syncthreads();

    if (tid < NCAND) {
        float t = 0.0f;
        #pragma unroll
        for (int k = 0; k < 8; k++) t += serr[tid * 8 + k];
        stot[tid] = t;
    }
    __syncthreads();

    // Sequential argmin, strict '<' => earliest candidate wins ties (scan order)
    if (tid == 0) {
        float best = stot[0];
        int bi = 0;
        for (int c = 1; c < NCAND; c++) {
            float e = stot[c];
            if (e < best) { best = e; bi = c; }
        }
        sscale = sS[bi];
    }
    __syncthreads();

    // ---- Final dequant (re-read row from gmem; DRAM ~2% utilized) ----
    const float s    = sscale;
    const float invs = 1.0f / s;
    float* __restrict__ orow = out + (size_t)row * NCOLS;
    #pragma unroll
    for (int k = 0; k < EPT; k++) {
        float v = wrow[tid + k * NTHREADS];
        float r = rintf(v * invs);
        r = fminf(fmaxf(r, -4.0f), 3.0f);
        orow[tid + k * NTHREADS] = s * r;
    }
}

extern "C" void kernel_launch(void* const* d_in, const int* in_sizes, int n_in,
                              void* d_out, int out_size) {
    (void)in_sizes; (void)n_in; (void)out_size;
    const float* w = (const float*)d_in[0];
    float* out = (float*)d_out;
    quant_search_kernel<<<NROWS, NTHREADS>>>(w, out);
}

// round 16
// speedup vs baseline: 1.0541x; 1.0541x over previous
#include <cuda_runtime.h>

// w: [4096, 4096] fp32. Hinv1 dead (LAMBDA=1.0), bit_width fixed at 3.
#define NROWS 4096
#define NCOLS 4096
#define NTHREADS 256
#define EPT (NCOLS / NTHREADS)
#define NCAND 101

__device__ __forceinline__ float fast_lg2(float x) {
    float y; asm("lg2.approx.f32 %0, %1;" : "=f"(y) : "f"(x)); return y;
}
__device__ __forceinline__ float fast_ex2(float x) {
    float y; asm("ex2.approx.f32 %0, %1;" : "=f"(y) : "f"(x)); return y;
}

// ---- packed f32x2 helpers (Blackwell sm_103a) ----
__device__ __forceinline__ unsigned long long pk2(float lo, float hi) {
    unsigned long long o;
    asm("mov.b64 %0, {%1, %2};" : "=l"(o) : "f"(lo), "f"(hi));
    return o;
}
__device__ __forceinline__ void upk2(float& lo, float& hi, unsigned long long p) {
    asm("mov.b64 {%0, %1}, %2;" : "=f"(lo), "=f"(hi) : "l"(p));
}
__device__ __forceinline__ unsigned long long mul2(unsigned long long a, unsigned long long b) {
    unsigned long long o;
    asm("mul.rn.f32x2 %0, %1, %2;" : "=l"(o) : "l"(a), "l"(b));
    return o;
}
__device__ __forceinline__ unsigned long long add2(unsigned long long a, unsigned long long b) {
    unsigned long long o;
    asm("add.rn.f32x2 %0, %1, %2;" : "=l"(o) : "l"(a), "l"(b));
    return o;
}
__device__ __forceinline__ unsigned long long sub2(unsigned long long a, unsigned long long b) {
    unsigned long long o;
    asm("sub.rn.f32x2 %0, %1, %2;" : "=l"(o) : "l"(a), "l"(b));
    return o;
}
__device__ __forceinline__ unsigned long long fma2(unsigned long long a, unsigned long long b,
                                                   unsigned long long c) {
    unsigned long long o;
    asm("fma.rn.f32x2 %0, %1, %2, %3;" : "=l"(o) : "l"(a), "l"(b), "l"(c));
    return o;
}
__device__ __forceinline__ unsigned long long abs2(unsigned long long a) {
    return a & 0x7FFFFFFF7FFFFFFFull;
}

// ---- f16x2 helpers ----
__device__ __forceinline__ unsigned cvt_f16x2(float hi, float lo) {
    unsigned r; asm("cvt.rn.f16x2.f32 %0, %1, %2;" : "=r"(r) : "f"(hi), "f"(lo));
    return r;
}
__device__ __forceinline__ unsigned ex2h2(unsigned x) {
    unsigned r; asm("ex2.approx.f16x2 %0, %1;" : "=r"(r) : "r"(x));
    return r;
}
__device__ __forceinline__ unsigned hadd2(unsigned a, unsigned b) {
    unsigned o; asm("add.rn.f16x2 %0, %1, %2;" : "=r"(o) : "r"(a), "r"(b));
    return o;
}
__device__ __forceinline__ void h2_to_f32(float& lo, float& hi, unsigned h) {
    asm("{\n\t.reg .b16 l, u;\n\t"
        "mov.b32 {l, u}, %2;\n\t"
        "cvt.f32.f16 %0, l;\n\t"
        "cvt.f32.f16 %1, u;\n\t}" : "=f"(lo), "=f"(hi) : "r"(h));
}

// Candidate shrink factors in reference scan order.
__device__ __forceinline__ float pcand(int c) {
    const float delta = 0.1f / 50.0f;
    if (c == 0) return 1.0f;
    if (c <= 50) return fmaf(delta, (float)c, 1.0f);
    return fmaf(-delta, (float)(c - 50), 1.0f);
}

#define MAGIC2 25165824.0f   // 3*2^23 : even-grain magic -> R = 2*rint(q/2)

// Degree-4 Chebyshev truncation of x^2.4 on [0,1], abs err <= ~4e-4.
#define Q0  0.000403f
#define Q1 -0.024680f
#define Q2  0.517810f
#define Q3  0.644350f
#define Q4 -0.138060f

__global__ __launch_bounds__(NTHREADS, 4) void quant_search_kernel(
    const float* __restrict__ w, float* __restrict__ out)
{
    __shared__ __align__(16) float sact[NCOLS];  // interior front, boundary back
    __shared__ float sS[NCAND];
    __shared__ float sI[NCAND];
    __shared__ float sC[NCAND];                  // (s/2)^2.4 * 2^B per candidate
    __shared__ float serr[NCAND * 8];
    __shared__ float stot[NCAND];
    __shared__ float smn[8], smx[8];
    __shared__ float sscale;
    __shared__ int   scnt_i, scnt_b;

    const int row  = blockIdx.x;
    const int tid  = threadIdx.x;
    const int lane = tid & 31;
    const int wid  = tid >> 5;
    const float* __restrict__ wrow = w + (size_t)row * NCOLS;

    if (tid == 0) { scnt_i = 0; scnt_b = 0; }

    // ---- Load row; min/max vs 0 (reference semantics) ----
    float wv[EPT];
    float mn = 0.0f, mx = 0.0f;
    #pragma unroll
    for (int k = 0; k < EPT; k++) {
        wv[k] = wrow[tid + k * NTHREADS];
        mn = fminf(mn, wv[k]);
        mx = fmaxf(mx, wv[k]);
    }
    #pragma unroll
    for (int o = 16; o > 0; o >>= 1) {
        mn = fminf(mn, __shfl_xor_sync(0xffffffffu, mn, o));
        mx = fmaxf(mx, __shfl_xor_sync(0xffffffffu, mx, o));
    }
    if (lane == 0) { smn[wid] = mn; smx[wid] = mx; }
    __syncthreads();

    float xmin = smn[0], xmax = smx[0];
    #pragma unroll
    for (int k = 1; k < 8; k++) {
        xmin = fminf(xmin, smn[k]);
        xmax = fmaxf(xmax, smx[k]);
    }
    if (xmin == 0.0f && xmax == 0.0f) { xmin = -1.0f; xmax = 1.0f; }
    const float rng = xmax - xmin;

    const float s_min = pcand(NCAND - 1) * rng / 7.0f;
    const float thr_p  = 0.49999f * s_min;   // prune: rint=0 for every candidate
    const float thr_hi = 3.4999f  * s_min;   // interior: clamp can never fire
    const float thr_lo = -4.4999f * s_min;

    // Per-row exponent bias (argmin-invariant global factor 2^B).
    const float B = fmaf(-2.4f, fast_lg2(rng), 11.5376f);

    if (tid < NCAND) {
        float s = pcand(tid) * rng / 7.0f;
        sS[tid] = s;
        sI[tid] = 1.0f / s;
        sC[tid] = fast_ex2(fmaf(2.4f, fast_lg2(0.5f * s), B));  // (s/2)^2.4 * 2^B
    }

    // ---- Two-class compaction (order irrelevant to fp-tolerant argmin) ----
    int ci = 0, cb = 0;
    #pragma unroll
    for (int k = 0; k < EPT; k++) {
        bool active = fabsf(wv[k]) > thr_p;
        bool inter  = active && (wv[k] < thr_hi) && (wv[k] > thr_lo);
        ci += inter ? 1 : 0;
        cb += (active && !inter) ? 1 : 0;
    }
    int bi_ = (ci > 0) ? atomicAdd(&scnt_i, ci) : 0;
    int bb_ = (cb > 0) ? atomicAdd(&scnt_b, cb) : 0;
    #pragma unroll
    for (int k = 0; k < EPT; k++) {
        bool active = fabsf(wv[k]) > thr_p;
        bool inter  = active && (wv[k] < thr_hi) && (wv[k] > thr_lo);
        if (inter) sact[bi_++] = wv[k];
        else if (active) sact[NCOLS - 1 - (bb_++)] = wv[k];
    }
    __syncthreads();
    const int nint   = scnt_i;
    const int nbnd   = scnt_b;
    const int nquads = nint >> 2;        // 4 elements per iteration
    const int ntail  = nint & 3;         // 0..3 interior leftovers -> scalar loop

    const unsigned long long MG2 = pk2(MAGIC2, MAGIC2);
    const unsigned long long C0 = pk2(Q0, Q0), C1 = pk2(Q1, Q1), C2 = pk2(Q2, Q2);
    const unsigned long long C3 = pk2(Q3, Q3), C4 = pk2(Q4, Q4);

    // ---- Candidate search: 25 tiles of 4 (2 f16-MUFU + 2 fma-poly-d4), then cand 100
    // All candidates use jj = 2/s and the even-grain magic: R = 2*rint(u).
    // f16 path: d = fma(-s/2, R, v) == fma(-s, r, v) bit-identically.
    for (int ct = 0; ct < NCAND - 1; ct += 4) {
        const float s0 = sS[ct],  s1 = sS[ct+1], s2 = sS[ct+2], s3 = sS[ct+3];
        const float i0 = sI[ct],  i1 = sI[ct+1], i2 = sI[ct+2], i3 = sI[ct+3];
        const float j0 = 2.0f * i0, j1 = 2.0f * i1, j2 = 2.0f * i2, j3 = 2.0f * i3;
        const unsigned long long jj0 = pk2(j0, j0), jj1 = pk2(j1, j1);
        const unsigned long long jj2 = pk2(j2, j2), jj3 = pk2(j3, j3);
        const float h0 = -0.5f * s0, h1 = -0.5f * s1;
        const unsigned long long nh0 = pk2(h0, h0), nh1 = pk2(h1, h1);
        // Dual accumulators per candidate (independent chains per quad-half)
        unsigned hc0a = 0u, hc0b = 0u, hc1a = 0u, hc1b = 0u;
        unsigned long long p2a = 0ull, p2b = 0ull, p3a = 0ull, p3b = 0ull;

        for (int i = tid; i < nquads; i += NTHREADS) {
            const float4 vq = reinterpret_cast<const float4*>(sact)[i];
            const unsigned long long v2a = pk2(vq.x, vq.y);
            const unsigned long long v2b = pk2(vq.z, vq.w);

            // f16 path: term = ex2_h16(2.4*lg2|d| + B), accumulated in f16x2.
            #define F16_STEP(jj, nh, v2, acc) do {                         \
                unsigned long long q = mul2(v2, jj);                       \
                unsigned long long R = sub2(add2(q, MG2), MG2);            \
                unsigned long long d = fma2(nh, R, v2);                    \
                float dl, dh; upk2(dl, dh, d);                             \
                float x0 = fmaf(2.4f, fast_lg2(fabsf(dl)), B);             \
                float x1 = fmaf(2.4f, fast_lg2(fabsf(dh)), B);             \
                acc = hadd2(acc, ex2h2(cvt_f16x2(x1, x0))); } while (0)
            F16_STEP(jj0, nh0, v2a, hc0a);
            F16_STEP(jj0, nh0, v2b, hc0b);
            F16_STEP(jj1, nh1, v2a, hc1a);
            F16_STEP(jj1, nh1, v2b, hc1b);
            #undef F16_STEP

            // Poly path: t = q - R = 2(u - r); term = P4(|t|), scaled by sC[c].
            #define POLY_STEP(jj, v2, acc) do {                            \
                unsigned long long q = mul2(v2, jj);                       \
                unsigned long long R = sub2(add2(q, MG2), MG2);            \
                unsigned long long t = sub2(q, R);                         \
                unsigned long long at = abs2(t);                           \
                unsigned long long pp = fma2(C4, at, C3);                  \
                pp = fma2(pp, at, C2);                                     \
                pp = fma2(pp, at, C1);                                     \
                pp = fma2(pp, at, C0);                                     \
                acc = add2(acc, pp); } while (0)
            POLY_STEP(jj2, v2a, p2a);
            POLY_STEP(jj2, v2b, p2b);
            POLY_STEP(jj3, v2a, p3a);
            POLY_STEP(jj3, v2b, p3b);
            #undef POLY_STEP
        }

        float a0, a1, a2, a3, tl, th;
        h2_to_f32(tl, th, hadd2(hc0a, hc0b)); a0 = tl + th;
        h2_to_f32(tl, th, hadd2(hc1a, hc1b)); a1 = tl + th;
        upk2(tl, th, add2(p2a, p2b));         a2 = (tl + th) * sC[ct+2];
        upk2(tl, th, add2(p3a, p3b));         a3 = (tl + th) * sC[ct+3];

        // Boundary (+ interior tail 0..3): scalar f32 MUFU with clamps, biased.
        // Clamps never fire for interior tail elements -> identical math.
        for (int j = tid; j < nbnd + ntail; j += NTHREADS) {
            const float v = (j < nbnd) ? sact[NCOLS - 1 - j]
                                       : sact[4 * nquads + (j - nbnd)];
            float r;
            r = fminf(fmaxf(rintf(v * i0), -4.0f), 3.0f);
            a0 += fast_ex2(fmaf(2.4f, fast_lg2(fabsf(fmaf(s0, r, -v))), B));
            r = fminf(fmaxf(rintf(v * i1), -4.0f), 3.0f);
            a1 += fast_ex2(fmaf(2.4f, fast_lg2(fabsf(fmaf(s1, r, -v))), B));
            r = fminf(fmaxf(rintf(v * i2), -4.0f), 3.0f);
            a2 += fast_ex2(fmaf(2.4f, fast_lg2(fabsf(fmaf(s2, r, -v))), B));
            r = fminf(fmaxf(rintf(v * i3), -4.0f), 3.0f);
            a3 += fast_ex2(fmaf(2.4f, fast_lg2(fabsf(fmaf(s3, r, -v))), B));
        }

        #pragma unroll
        for (int o = 16; o > 0; o >>= 1) {
            a0 += __shfl_xor_sync(0xffffffffu, a0, o);
            a1 += __shfl_xor_sync(0xffffffffu, a1, o);
            a2 += __shfl_xor_sync(0xffffffffu, a2, o);
            a3 += __shfl_xor_sync(0xffffffffu, a3, o);
        }
        if (lane == 0) {
            serr[(ct    ) * 8 + wid] = a0;
            serr[(ct + 1) * 8 + wid] = a1;
            serr[(ct + 2) * 8 + wid] = a2;
            serr[(ct + 3) * 8 + wid] = a3;
        }
    }
    {   // candidate 100: scalar f32 MUFU path, biased
        const int c = NCAND - 1;
        const float s = sS[c], is = sI[c];
        float a = 0.0f;
        for (int i = tid; i < nint; i += NTHREADS) {
            const float v = sact[i];
            float r = rintf(v * is);
            a += fast_ex2(fmaf(2.4f, fast_lg2(fabsf(fmaf(s, r, -v))), B));
        }
        for (int j = tid; j < nbnd; j += NTHREADS) {
            const float v = sact[NCOLS - 1 - j];
            float r = fminf(fmaxf(rintf(v * is), -4.0f), 3.0f);
            a += fast_ex2(fmaf(2.4f, fast_lg2(fabsf(fmaf(s, r, -v))), B));
        }
        #pragma unroll
        for (int o = 16; o > 0; o >>= 1) a += __shfl_xor_sync(0xffffffffu, a, o);
        if (lane == 0) serr[c * 8 + wid] = a;
    }
    __syncthreads();

    if (tid < NCAND) {
        float t = 0.0f;
        #pragma unroll
        for (int k = 0; k < 8; k++) t += serr[tid * 8 + k];
        stot[tid] = t;
    }
    __syncthreads();

    // Sequential argmin, strict '<' => earliest candidate wins ties (scan order)
    if (tid == 0) {
        float best = stot[0];
        int bi = 0;
        for (int c = 1; c < NCAND; c++) {
            float e = stot[c];
            if (e < best) { best = e; bi = c; }
        }
        sscale = sS[bi];
    }
    __syncthreads();

    // ---- Final dequant (re-read row from gmem; DRAM ~2% utilized) ----
    const float s    = sscale;
    const float invs = 1.0f / s;
    float* __restrict__ orow = out + (size_t)row * NCOLS;
    #pragma unroll
    for (int k = 0; k < EPT; k++) {
        float v = wrow[tid + k * NTHREADS];
        float r = rintf(v * invs);
        r = fminf(fmaxf(r, -4.0f), 3.0f);
        orow[tid + k * NTHREADS] = s * r;
    }
}

extern "C" void kernel_launch(void* const* d_in, const int* in_sizes, int n_in,
                              void* d_out, int out_size) {
    (void)in_sizes; (void)n_in; (void)out_size;
    const float* w = (const float*)d_in[0];
    float* out = (float*)d_out;
    quant_search_kernel<<<NROWS, NTHREADS>>>(w, out);
}

// round 17
// speedup vs baseline: 1.0766x; 1.0213x over previous
#include <cuda_runtime.h>

// w: [4096, 4096] fp32. Hinv1 dead (LAMBDA=1.0), bit_width fixed at 3.
#define NROWS 4096
#define NCOLS 4096
#define NTHREADS 256
#define EPT (NCOLS / NTHREADS)
#define NCAND 101

__device__ __forceinline__ float fast_lg2(float x) {
    float y; asm("lg2.approx.f32 %0, %1;" : "=f"(y) : "f"(x)); return y;
}
__device__ __forceinline__ float fast_ex2(float x) {
    float y; asm("ex2.approx.f32 %0, %1;" : "=f"(y) : "f"(x)); return y;
}

// ---- packed f32x2 helpers (Blackwell sm_103a) ----
__device__ __forceinline__ unsigned long long pk2(float lo, float hi) {
    unsigned long long o;
    asm("mov.b64 %0, {%1, %2};" : "=l"(o) : "f"(lo), "f"(hi));
    return o;
}
__device__ __forceinline__ void upk2(float& lo, float& hi, unsigned long long p) {
    asm("mov.b64 {%0, %1}, %2;" : "=f"(lo), "=f"(hi) : "l"(p));
}
__device__ __forceinline__ unsigned long long mul2(unsigned long long a, unsigned long long b) {
    unsigned long long o;
    asm("mul.rn.f32x2 %0, %1, %2;" : "=l"(o) : "l"(a), "l"(b));
    return o;
}
__device__ __forceinline__ unsigned long long add2(unsigned long long a, unsigned long long b) {
    unsigned long long o;
    asm("add.rn.f32x2 %0, %1, %2;" : "=l"(o) : "l"(a), "l"(b));
    return o;
}
__device__ __forceinline__ unsigned long long sub2(unsigned long long a, unsigned long long b) {
    unsigned long long o;
    asm("sub.rn.f32x2 %0, %1, %2;" : "=l"(o) : "l"(a), "l"(b));
    return o;
}
__device__ __forceinline__ unsigned long long fma2(unsigned long long a, unsigned long long b,
                                                   unsigned long long c) {
    unsigned long long o;
    asm("fma.rn.f32x2 %0, %1, %2, %3;" : "=l"(o) : "l"(a), "l"(b), "l"(c));
    return o;
}
__device__ __forceinline__ unsigned long long abs2(unsigned long long a) {
    return a & 0x7FFFFFFF7FFFFFFFull;
}

// ---- f16x2 helpers ----
__device__ __forceinline__ unsigned cvt_f16x2(float hi, float lo) {
    unsigned r; asm("cvt.rn.f16x2.f32 %0, %1, %2;" : "=r"(r) : "f"(hi), "f"(lo));
    return r;
}
__device__ __forceinline__ unsigned ex2h2(unsigned x) {
    unsigned r; asm("ex2.approx.f16x2 %0, %1;" : "=r"(r) : "r"(x));
    return r;
}
__device__ __forceinline__ unsigned hadd2(unsigned a, unsigned b) {
    unsigned o; asm("add.rn.f16x2 %0, %1, %2;" : "=r"(o) : "r"(a), "r"(b));
    return o;
}
__device__ __forceinline__ void h2_to_f32(float& lo, float& hi, unsigned h) {
    asm("{\n\t.reg .b16 l, u;\n\t"
        "mov.b32 {l, u}, %2;\n\t"
        "cvt.f32.f16 %0, l;\n\t"
        "cvt.f32.f16 %1, u;\n\t}" : "=f"(lo), "=f"(hi) : "r"(h));
}

// Candidate shrink factors in reference scan order.
__device__ __forceinline__ float pcand(int c) {
    const float delta = 0.1f / 50.0f;
    if (c == 0) return 1.0f;
    if (c <= 50) return fmaf(delta, (float)c, 1.0f);
    return fmaf(-delta, (float)(c - 50), 1.0f);
}

#define MAGIC2 25165824.0f   // 3*2^23 : even-grain magic -> R = 2*rint(q/2)

// Degree-4 Chebyshev truncation of x^2.4 on [0,1], abs err <= ~4e-4.
#define Q0  0.000403f
#define Q1 -0.024680f
#define Q2  0.517810f
#define Q3  0.644350f
#define Q4 -0.138060f

__global__ __launch_bounds__(NTHREADS, 4) void quant_search_kernel(
    const float* __restrict__ w, float* __restrict__ out)
{
    __shared__ __align__(16) float sact[NCOLS];  // interior front, boundary back
    __shared__ float sS[NCAND];
    __shared__ float sI[NCAND];
    __shared__ float sC[NCAND];                  // (s/2)^2.4 * 2^B per candidate
    __shared__ float serr[NCAND * 8];
    __shared__ float stot[NCAND];
    __shared__ float smn[8], smx[8];
    __shared__ float sscale;
    __shared__ int   scnt_i, scnt_b;

    const int row  = blockIdx.x;
    const int tid  = threadIdx.x;
    const int lane = tid & 31;
    const int wid  = tid >> 5;
    const float* __restrict__ wrow = w + (size_t)row * NCOLS;

    if (tid == 0) { scnt_i = 0; scnt_b = 0; }

    // ---- Load row; min/max vs 0 (reference semantics) ----
    float wv[EPT];
    float mn = 0.0f, mx = 0.0f;
    #pragma unroll
    for (int k = 0; k < EPT; k++) {
        wv[k] = wrow[tid + k * NTHREADS];
        mn = fminf(mn, wv[k]);
        mx = fmaxf(mx, wv[k]);
    }
    #pragma unroll
    for (int o = 16; o > 0; o >>= 1) {
        mn = fminf(mn, __shfl_xor_sync(0xffffffffu, mn, o));
        mx = fmaxf(mx, __shfl_xor_sync(0xffffffffu, mx, o));
    }
    if (lane == 0) { smn[wid] = mn; smx[wid] = mx; }
    __syncthreads();

    float xmin = smn[0], xmax = smx[0];
    #pragma unroll
    for (int k = 1; k < 8; k++) {
        xmin = fminf(xmin, smn[k]);
        xmax = fmaxf(xmax, smx[k]);
    }
    if (xmin == 0.0f && xmax == 0.0f) { xmin = -1.0f; xmax = 1.0f; }
    const float rng = xmax - xmin;

    const float s_min = pcand(NCAND - 1) * rng / 7.0f;
    const float thr_p  = 0.49999f * s_min;   // prune: rint=0 for every candidate
    const float thr_hi = 3.4999f  * s_min;   // interior: clamp can never fire
    const float thr_lo = -4.4999f * s_min;

    // Per-row exponent bias (argmin-invariant global factor 2^B).
    const float B = fmaf(-2.4f, fast_lg2(rng), 11.5376f);

    if (tid < NCAND) {
        float s = pcand(tid) * rng / 7.0f;
        sS[tid] = s;
        sI[tid] = 1.0f / s;
        sC[tid] = fast_ex2(fmaf(2.4f, fast_lg2(0.5f * s), B));  // (s/2)^2.4 * 2^B
    }

    // ---- Two-class compaction (order irrelevant to fp-tolerant argmin) ----
    int ci = 0, cb = 0;
    #pragma unroll
    for (int k = 0; k < EPT; k++) {
        bool active = fabsf(wv[k]) > thr_p;
        bool inter  = active && (wv[k] < thr_hi) && (wv[k] > thr_lo);
        ci += inter ? 1 : 0;
        cb += (active && !inter) ? 1 : 0;
    }
    int bi_ = (ci > 0) ? atomicAdd(&scnt_i, ci) : 0;
    int bb_ = (cb > 0) ? atomicAdd(&scnt_b, cb) : 0;
    #pragma unroll
    for (int k = 0; k < EPT; k++) {
        bool active = fabsf(wv[k]) > thr_p;
        bool inter  = active && (wv[k] < thr_hi) && (wv[k] > thr_lo);
        if (inter) sact[bi_++] = wv[k];
        else if (active) sact[NCOLS - 1 - (bb_++)] = wv[k];
    }
    __syncthreads();
    const int nint   = scnt_i;
    const int nbnd   = scnt_b;
    const int nquads = nint >> 2;        // 4 elements per iteration
    const int ntail  = nint & 3;         // 0..3 interior leftovers -> scalar loop

    const unsigned long long MG2 = pk2(MAGIC2, MAGIC2);
    const unsigned long long C0 = pk2(Q0, Q0), C1 = pk2(Q1, Q1), C2 = pk2(Q2, Q2);
    const unsigned long long C3 = pk2(Q3, Q3), C4 = pk2(Q4, Q4);

    // ---- Candidate search: 25 tiles of 4 (2 f16-MUFU + 2 fma-poly-d4), then cand 100
    // All candidates use jj = 2/s and the even-grain magic: R = 2*rint(u).
    // f16 path: d = fma(-s/2, R, v) == fma(-s, r, v) bit-identically.
    for (int ct = 0; ct < NCAND - 1; ct += 4) {
        const float s0 = sS[ct],  s1 = sS[ct+1], s2 = sS[ct+2], s3 = sS[ct+3];
        const float i0 = sI[ct],  i1 = sI[ct+1], i2 = sI[ct+2], i3 = sI[ct+3];
        const float j0 = 2.0f * i0, j1 = 2.0f * i1, j2 = 2.0f * i2, j3 = 2.0f * i3;
        const unsigned long long jj0 = pk2(j0, j0), jj1 = pk2(j1, j1);
        const unsigned long long jj2 = pk2(j2, j2), jj3 = pk2(j3, j3);
        const float h0 = -0.5f * s0, h1 = -0.5f * s1;
        const unsigned long long nh0 = pk2(h0, h0), nh1 = pk2(h1, h1);
        // Dual accumulators per candidate (independent chains per quad-half)
        unsigned hc0a = 0u, hc0b = 0u, hc1a = 0u, hc1b = 0u;
        unsigned long long p2a = 0ull, p2b = 0ull, p3a = 0ull, p3b = 0ull;

        for (int i = tid; i < nquads; i += NTHREADS) {
            const float4 vq = reinterpret_cast<const float4*>(sact)[i];
            const unsigned long long v2a = pk2(vq.x, vq.y);
            const unsigned long long v2b = pk2(vq.z, vq.w);

            // f16 path: term = ex2_h16(2.4*lg2|d| + B), accumulated in f16x2.
            #define F16_STEP(jj, nh, v2, acc) do {                         \
                unsigned long long q = mul2(v2, jj);                       \
                unsigned long long R = sub2(add2(q, MG2), MG2);            \
                unsigned long long d = fma2(nh, R, v2);                    \
                float dl, dh; upk2(dl, dh, d);                             \
                float x0 = fmaf(2.4f, fast_lg2(fabsf(dl)), B);             \
                float x1 = fmaf(2.4f, fast_lg2(fabsf(dh)), B);             \
                acc = hadd2(acc, ex2h2(cvt_f16x2(x1, x0))); } while (0)
            F16_STEP(jj0, nh0, v2a, hc0a);
            F16_STEP(jj0, nh0, v2b, hc0b);
            F16_STEP(jj1, nh1, v2a, hc1a);
            F16_STEP(jj1, nh1, v2b, hc1b);
            #undef F16_STEP

            // Poly path: t = q - R = 2(u - r); term = P4(|t|), scaled by sC[c].
            #define POLY_STEP(jj, v2, acc) do {                            \
                unsigned long long q = mul2(v2, jj);                       \
                unsigned long long R = sub2(add2(q, MG2), MG2);            \
                unsigned long long t = sub2(q, R);                         \
                unsigned long long at = abs2(t);                           \
                unsigned long long pp = fma2(C4, at, C3);                  \
                pp = fma2(pp, at, C2);                                     \
                pp = fma2(pp, at, C1);                                     \
                pp = fma2(pp, at, C0);                                     \
                acc = add2(acc, pp); } while (0)
            POLY_STEP(jj2, v2a, p2a);
            POLY_STEP(jj2, v2b, p2b);
            POLY_STEP(jj3, v2a, p3a);
            POLY_STEP(jj3, v2b, p3b);
            #undef POLY_STEP
        }

        float a0, a1, a2, a3, tl, th;
        h2_to_f32(tl, th, hadd2(hc0a, hc0b)); a0 = tl + th;
        h2_to_f32(tl, th, hadd2(hc1a, hc1b)); a1 = tl + th;
        upk2(tl, th, add2(p2a, p2b));         a2 = (tl + th) * sC[ct+2];
        upk2(tl, th, add2(p3a, p3b));         a3 = (tl + th) * sC[ct+3];

        // Boundary (+ interior tail 0..3): scalar f32 MUFU with clamps, biased.
        // Clamps never fire for interior tail elements -> identical math.
        for (int j = tid; j < nbnd + ntail; j += NTHREADS) {
            const float v = (j < nbnd) ? sact[NCOLS - 1 - j]
                                       : sact[4 * nquads + (j - nbnd)];
            float r;
            r = fminf(fmaxf(rintf(v * i0), -4.0f), 3.0f);
            a0 += fast_ex2(fmaf(2.4f, fast_lg2(fabsf(fmaf(s0, r, -v))), B));
            r = fminf(fmaxf(rintf(v * i1), -4.0f), 3.0f);
            a1 += fast_ex2(fmaf(2.4f, fast_lg2(fabsf(fmaf(s1, r, -v))), B));
            r = fminf(fmaxf(rintf(v * i2), -4.0f), 3.0f);
            a2 += fast_ex2(fmaf(2.4f, fast_lg2(fabsf(fmaf(s2, r, -v))), B));
            r = fminf(fmaxf(rintf(v * i3), -4.0f), 3.0f);
            a3 += fast_ex2(fmaf(2.4f, fast_lg2(fabsf(fmaf(s3, r, -v))), B));
        }

        #pragma unroll
        for (int o = 16; o > 0; o >>= 1) {
            a0 += __shfl_xor_sync(0xffffffffu, a0, o);
            a1 += __shfl_xor_sync(0xffffffffu, a1, o);
            a2 += __shfl_xor_sync(0xffffffffu, a2, o);
            a3 += __shfl_xor_sync(0xffffffffu, a3, o);
        }
        if (lane == 0) {
            serr[(ct    ) * 8 + wid] = a0;
            serr[(ct + 1) * 8 + wid] = a1;
            serr[(ct + 2) * 8 + wid] = a2;
            serr[(ct + 3) * 8 + wid] = a3;
        }
    }
    {   // candidate 100: packed d4-poly quad loop (fma-only, cheapest path)
        const int c = NCAND - 1;
        const float s = sS[c], is = sI[c];
        const float jc = 2.0f * is;
        const unsigned long long jjc = pk2(jc, jc);
        unsigned long long pa = 0ull, pb = 0ull;
        for (int i = tid; i < nquads; i += NTHREADS) {
            const float4 vq = reinterpret_cast<const float4*>(sact)[i];
            const unsigned long long v2a = pk2(vq.x, vq.y);
            const unsigned long long v2b = pk2(vq.z, vq.w);
            {
                unsigned long long q = mul2(v2a, jjc);
                unsigned long long R = sub2(add2(q, MG2), MG2);
                unsigned long long t = sub2(q, R);
                unsigned long long at = abs2(t);
                unsigned long long pp = fma2(C4, at, C3);
                pp = fma2(pp, at, C2);
                pp = fma2(pp, at, C1);
                pp = fma2(pp, at, C0);
                pa = add2(pa, pp);
            }
            {
                unsigned long long q = mul2(v2b, jjc);
                unsigned long long R = sub2(add2(q, MG2), MG2);
                unsigned long long t = sub2(q, R);
                unsigned long long at = abs2(t);
                unsigned long long pp = fma2(C4, at, C3);
                pp = fma2(pp, at, C2);
                pp = fma2(pp, at, C1);
                pp = fma2(pp, at, C0);
                pb = add2(pb, pp);
            }
        }
        float tl, th;
        upk2(tl, th, add2(pa, pb));
        float a = (tl + th) * sC[c];
        // Boundary (+ interior tail): scalar f32 MUFU with clamps, biased.
        for (int j = tid; j < nbnd + ntail; j += NTHREADS) {
            const float v = (j < nbnd) ? sact[NCOLS - 1 - j]
                                       : sact[4 * nquads + (j - nbnd)];
            float r = fminf(fmaxf(rintf(v * is), -4.0f), 3.0f);
            a += fast_ex2(fmaf(2.4f, fast_lg2(fabsf(fmaf(s, r, -v))), B));
        }
        #pragma unroll
        for (int o = 16; o > 0; o >>= 1) a += __shfl_xor_sync(0xffffffffu, a, o);
        if (lane == 0) serr[c * 8 + wid] = a;
    }
    __syncthreads();

    if (tid < NCAND) {
        float t = 0.0f;
        #pragma unroll
        for (int k = 0; k < 8; k++) t += serr[tid * 8 + k];
        stot[tid] = t;
    }
    __syncthreads();

    // Sequential argmin, strict '<' => earliest candidate wins ties (scan order)
    if (tid == 0) {
        float best = stot[0];
        int bi = 0;
        for (int c = 1; c < NCAND; c++) {
            float e = stot[c];
            if (e < best) { best = e; bi = c; }
        }
        sscale = sS[bi];
    }
    __syncthreads();

    // ---- Final dequant (re-read row from gmem; DRAM ~2% utilized) ----
    const float s    = sscale;
    const float invs = 1.0f / s;
    float* __restrict__ orow = out + (size_t)row * NCOLS;
    #pragma unroll
    for (int k = 0; k < EPT; k++) {
        float v = wrow[tid + k * NTHREADS];
        float r = rintf(v * invs);
        r = fminf(fmaxf(r, -4.0f), 3.0f);
        orow[tid + k * NTHREADS] = s * r;
    }
}

extern "C" void kernel_launch(void* const* d_in, const int* in_sizes, int n_in,
                              void* d_out, int out_size) {
    (void)in_sizes; (void)n_in; (void)out_size;
    const float* w = (const float*)d_in[0];
    float* out = (float*)d_out;
    quant_search_kernel<<<NROWS, NTHREADS>>>(w, out);
}